// round 16
// baseline (speedup 1.0000x reference)
#include <cuda_runtime.h>
#include <cuda_fp16.h>
#include <math.h>
#include <stdint.h>

#define DIMX 1024
#define COND_DIM 512
#define HEADS 32
#define DIM_HEAD 32
#define NTOK 65
#define B_TOT 512
#define B_IMG 16
#define M_TOK (B_TOT * NTOK)
#define TWO_DIM (2 * DIMX)
#define NN (NTOK * NTOK)

__device__ float  g_h1[B_IMG * TWO_DIM];
__device__ float  g_gb[B_IMG * TWO_DIM];
__device__ __half g_xnh[(size_t)M_TOK * DIMX];
__device__ __half g_qkvh[(size_t)M_TOK * 3 * DIMX];
__device__ __half g_oh[(size_t)M_TOK * DIMX];
__device__ __half g_wqkvT[(size_t)3 * DIMX * DIMX];
__device__ __half g_woutT[(size_t)DIMX * DIMX];
__device__ float  g_bias[HEADS * NN];

#define CPA16(d, s) asm volatile("cp.async.cg.shared.global [%0], [%1], 16;" :: "r"(d), "l"(s) : "memory")
#define CPC()   asm volatile("cp.async.commit_group;" ::: "memory")
#define CPW0()  asm volatile("cp.async.wait_group 0;" ::: "memory")
#define CPW1()  asm volatile("cp.async.wait_group 1;" ::: "memory")
#define LDSM4(r0,r1,r2,r3,a) asm volatile( \
    "ldmatrix.sync.aligned.m8n8.x4.shared.b16 {%0,%1,%2,%3}, [%4];" \
    : "=r"(r0),"=r"(r1),"=r"(r2),"=r"(r3) : "r"(a))

__device__ __forceinline__ uint32_t smem_u32(const void* p) {
    uint32_t a; asm("{ .reg .u64 t; cvta.to.shared.u64 t, %1; cvt.u32.u64 %0, t; }" : "=r"(a) : "l"(p));
    return a;
}
__device__ __forceinline__ void mma_f16(float* d, const uint32_t* a, const uint32_t* b) {
    asm volatile(
        "mma.sync.aligned.m16n8k16.row.col.f32.f16.f16.f32 "
        "{%0,%1,%2,%3}, {%4,%5,%6,%7}, {%8,%9}, {%0,%1,%2,%3};\n"
        : "+f"(d[0]), "+f"(d[1]), "+f"(d[2]), "+f"(d[3])
        : "r"(a[0]), "r"(a[1]), "r"(a[2]), "r"(a[3]), "r"(b[0]), "r"(b[1]));
}

// ---- prep: wtrans (4096) + film1 (128) + bias (17) ----
__global__ __launch_bounds__(256) void prep_kernel(
    const float* __restrict__ Wq, const float* __restrict__ Wo,
    const float* __restrict__ cond, const float* __restrict__ w1, const float* __restrict__ b1,
    const float* __restrict__ rel_emb, const int* __restrict__ rel_idx)
{
    const int bx = blockIdx.x, t = threadIdx.x;
    if (bx < 4096) {
        __shared__ float tbuf[32][33];
        int bxx = bx & 127, byy = bx >> 7;
        int tx = t & 31, ty = t >> 5;
        const float* W;
        __half* WT;
        int N, n0;
        if (bxx < 96) { W = Wq; WT = g_wqkvT; N = 3 * DIMX; n0 = bxx * 32; }
        else          { W = Wo; WT = g_woutT; N = DIMX;     n0 = (bxx - 96) * 32; }
        int k0 = byy * 32;
        #pragma unroll
        for (int r = 0; r < 32; r += 8)
            tbuf[ty + r][tx] = W[(size_t)(k0 + ty + r) * N + n0 + tx];
        __syncthreads();
        #pragma unroll
        for (int r = 0; r < 32; r += 8)
            WT[(size_t)(n0 + ty + r) * DIMX + k0 + tx] = __float2half_rn(tbuf[tx][ty + r]);
    } else if (bx < 4096 + 128) {
        __shared__ float cs[COND_DIM];
        int i = (bx - 4096) >> 3, jb = (bx - 4096) & 7;
        int j = jb * 256 + t;
        for (int k = t; k < COND_DIM; k += 256) cs[k] = cond[i * COND_DIM + k];
        __syncthreads();
        float acc = b1[j];
        #pragma unroll 8
        for (int k = 0; k < COND_DIM; k++)
            acc = fmaf(cs[k], w1[(size_t)k * TWO_DIM + j], acc);
        g_h1[i * TWO_DIM + j] = acc / (1.f + __expf(-acc));
    } else {
        int e = (bx - 4096 - 128) * 256 + t;
        if (e < NN) {
            const float* re = rel_emb + (size_t)rel_idx[e] * HEADS;
            #pragma unroll
            for (int h = 0; h < HEADS; h++) g_bias[h * NN + e] = re[h];
        }
    }
}

// ---- FiLM stage 2 ----
__global__ __launch_bounds__(256) void film2_kernel(
    const float* __restrict__ w2, const float* __restrict__ b2)
{
    __shared__ float hs[TWO_DIM];
    int t = threadIdx.x, i = blockIdx.y;
    int j = blockIdx.x * 256 + t;
    for (int k = t; k < TWO_DIM; k += 256) hs[k] = g_h1[i * TWO_DIM + k];
    __syncthreads();
    float acc = b2[j];
    #pragma unroll 8
    for (int k = 0; k < TWO_DIM; k++)
        acc = fmaf(hs[k], w2[(size_t)k * TWO_DIM + j], acc);
    g_gb[i * TWO_DIM + j] = acc;
}

// ---- LayerNorm + FiLM -> half ----
__global__ __launch_bounds__(256) void ln_film_kernel(const float* __restrict__ x)
{
    int row = blockIdx.x;
    int img = (row / NTOK) >> 5;
    const float4* xr = (const float4*)(x + (size_t)row * DIMX);
    int t = threadIdx.x;
    float4 v = xr[t];
    float s = v.x + v.y + v.z + v.w;
    float ss = v.x*v.x + v.y*v.y + v.z*v.z + v.w*v.w;
    __shared__ float rs_[8], rss[8];
    #pragma unroll
    for (int o = 16; o > 0; o >>= 1) {
        s += __shfl_down_sync(~0u, s, o); ss += __shfl_down_sync(~0u, ss, o);
    }
    int warp = t >> 5, lane = t & 31;
    if (lane == 0) { rs_[warp] = s; rss[warp] = ss; }
    __syncthreads();
    if (warp == 0) {
        s = (lane < 8) ? rs_[lane] : 0.f; ss = (lane < 8) ? rss[lane] : 0.f;
        #pragma unroll
        for (int o = 4; o > 0; o >>= 1) {
            s += __shfl_down_sync(~0u, s, o); ss += __shfl_down_sync(~0u, ss, o);
        }
        if (lane == 0) { rs_[0] = s; rss[0] = ss; }
    }
    __syncthreads();
    float mu = rs_[0] * (1.f / DIMX);
    float var = rss[0] * (1.f / DIMX) - mu * mu;
    float rstd = rsqrtf(var + 1e-5f);
    const float4* gam = (const float4*)(g_gb + (size_t)img * TWO_DIM);
    const float4* bet = (const float4*)(g_gb + (size_t)img * TWO_DIM + DIMX);
    float4 gv = gam[t], bv = bet[t];
    __half2 h0 = __floats2half2_rn(fmaf((v.x - mu) * rstd, gv.x, bv.x),
                                   fmaf((v.y - mu) * rstd, gv.y, bv.y));
    __half2 h1 = __floats2half2_rn(fmaf((v.z - mu) * rstd, gv.z, bv.z),
                                   fmaf((v.w - mu) * rstd, gv.w, bv.w));
    ((__half2*)(g_xnh + (size_t)row * DIMX))[t * 2]     = h0;
    ((__half2*)(g_xnh + (size_t)row * DIMX))[t * 2 + 1] = h1;
}

// ---- fp16 GEMM 128x128x64, 3-stage cp.async, single barrier, LDSM4 for A and B ----
#define ASTR 72
#define TILE_B (128 * ASTR * 2)      // 18432
#define STG_B (2 * TILE_B)           // 36864
#define HG_SMEM (3 * STG_B)          // 110592

template <int FUSE>
__global__ __launch_bounds__(256, 2) void hgemm_kernel(
    const __half* __restrict__ A, const __half* __restrict__ Bt,
    void* __restrict__ Cv, const float* __restrict__ qgam,
    const float* __restrict__ kgam, int N, int K)
{
    extern __shared__ char sm[];
    const uint32_t sb = smem_u32(sm);
    const int tid = threadIdx.x, warp = tid >> 5, lane = tid & 31;
    const int g = lane >> 2, tig = lane & 3;
    const int wm = (warp & 1) * 64, wn = (warp >> 1) * 32;
    const int row0 = blockIdx.y * 128, col0 = blockIdx.x * 128;

    float acc[4][4][4];
    #pragma unroll
    for (int mi = 0; mi < 4; mi++)
        #pragma unroll
        for (int nj = 0; nj < 4; nj++)
            #pragma unroll
            for (int c = 0; c < 4; c++) acc[mi][nj][c] = 0.f;

    const uint32_t laneA  = (uint32_t)((lane & 15) * 144 + (lane >> 4) * 16);
    const uint32_t laneB4 = (uint32_t)(((lane & 7) + ((lane >> 4) << 3)) * 144 + ((lane >> 3) & 1) * 16);

    const int KITERS = K >> 6;
    #pragma unroll
    for (int s = 0; s < 2; s++) {
        const int k0 = s << 6;
        #pragma unroll
        for (int p = 0; p < 4; p++) {
            int c = tid + 256 * p;
            int row = c >> 3, off = c & 7;
            CPA16(sb + s * STG_B + row * 144 + off * 16,
                  A + (size_t)(row0 + row) * K + k0 + off * 8);
            CPA16(sb + s * STG_B + TILE_B + row * 144 + off * 16,
                  Bt + (size_t)(col0 + row) * K + k0 + off * 8);
        }
        CPC();
    }
    int s_rd = 0, s_wr = 2;
    for (int kt = 0; kt < KITERS; kt++) {
        if (kt >= KITERS - 2) { CPW0(); } else { CPW1(); }
        __syncthreads();
        if (kt + 2 < KITERS) {
            const int k0 = (kt + 2) << 6;
            #pragma unroll
            for (int p = 0; p < 4; p++) {
                int c = tid + 256 * p;
                int row = c >> 3, off = c & 7;
                CPA16(sb + s_wr * STG_B + row * 144 + off * 16,
                      A + (size_t)(row0 + row) * K + k0 + off * 8);
                CPA16(sb + s_wr * STG_B + TILE_B + row * 144 + off * 16,
                      Bt + (size_t)(col0 + row) * K + k0 + off * 8);
            }
            CPC();
        }
        const uint32_t stA = sb + s_rd * STG_B;
        const uint32_t stB = stA + TILE_B;
        #pragma unroll
        for (int kk = 0; kk < 4; kk++) {
            uint32_t af[4][4], bf[4][2];
            #pragma unroll
            for (int mi = 0; mi < 4; mi++) {
                uint32_t a = stA + (uint32_t)(wm + mi * 16) * 144 + kk * 32 + laneA;
                LDSM4(af[mi][0], af[mi][1], af[mi][2], af[mi][3], a);
            }
            #pragma unroll
            for (int njp = 0; njp < 2; njp++) {
                uint32_t a = stB + (uint32_t)(wn + njp * 16) * 144 + kk * 32 + laneB4;
                LDSM4(bf[2*njp][0], bf[2*njp][1], bf[2*njp+1][0], bf[2*njp+1][1], a);
            }
            #pragma unroll
            for (int mi = 0; mi < 4; mi++)
                #pragma unroll
                for (int nj = 0; nj < 4; nj++)
                    mma_f16(acc[mi][nj], af[mi], bf[nj]);
        }
        s_rd = (s_rd == 2) ? 0 : s_rd + 1;
        s_wr = (s_wr == 2) ? 0 : s_wr + 1;
    }
    if (FUSE == 0) {
        float* C = (float*)Cv;
        #pragma unroll
        for (int mi = 0; mi < 4; mi++) {
            #pragma unroll
            for (int nj = 0; nj < 4; nj++) {
                int r = row0 + wm + mi * 16 + g;
                int c = col0 + wn + nj * 8 + tig * 2;
                *(float2*)(C + (size_t)r * N + c)       = make_float2(acc[mi][nj][0], acc[mi][nj][1]);
                *(float2*)(C + (size_t)(r + 8) * N + c) = make_float2(acc[mi][nj][2], acc[mi][nj][3]);
            }
        }
    } else {
        __half* C = (__half*)Cv;
        const int gcol0 = col0 + wn;
        const int sec = gcol0 >> 10;
        const int head = (gcol0 & 1023) >> 5;
        float gam[8];
        #pragma unroll
        for (int nj = 0; nj < 4; nj++) {
            int d = nj * 8 + tig * 2;
            if (sec == 0)      { gam[nj*2] = qgam[head*32+d]; gam[nj*2+1] = qgam[head*32+d+1]; }
            else if (sec == 1) { gam[nj*2] = kgam[head*32+d]; gam[nj*2+1] = kgam[head*32+d+1]; }
            else               { gam[nj*2] = 1.f; gam[nj*2+1] = 1.f; }
        }
        #pragma unroll
        for (int mi = 0; mi < 4; mi++) {
            #pragma unroll
            for (int hf = 0; hf < 2; hf++) {
                int r = row0 + wm + mi * 16 + g + hf * 8;
                float ss = 0.f;
                #pragma unroll
                for (int nj = 0; nj < 4; nj++) {
                    float a0 = acc[mi][nj][hf*2], a1 = acc[mi][nj][hf*2+1];
                    ss = fmaf(a0, a0, ss); ss = fmaf(a1, a1, ss);
                }
                ss += __shfl_xor_sync(~0u, ss, 1);
                ss += __shfl_xor_sync(~0u, ss, 2);
                float sc = (sec < 2) ? 5.656854249f / fmaxf(sqrtf(ss), 1e-12f) : 1.f;
                #pragma unroll
                for (int nj = 0; nj < 4; nj++) {
                    __half2 h2 = __floats2half2_rn(acc[mi][nj][hf*2]   * sc * gam[nj*2],
                                                   acc[mi][nj][hf*2+1] * sc * gam[nj*2+1]);
                    *(__half2*)(C + (size_t)r * 3072 + gcol0 + nj * 8 + tig * 2) = h2;
                }
            }
        }
    }
}

// ---- attention: fp16 smem tiles, 4x8 sim tiles, 4x8 PV tiles, fp32 accum ----
__global__ __launch_bounds__(256) void attn_kernel()
{
    int b = blockIdx.x, h = blockIdx.y;
    __shared__ __align__(16) float  psT[68 * 68];       // [j][i]
    __shared__ __align__(16) __half qTh[32 * 72];       // [d][i]
    __shared__ __align__(16) __half kTh[32 * 72];       // [d][j]
    __shared__ __align__(16) __half vsph[NTOK * 40];    // [n][d]

    int t = threadIdx.x;
    // zero-pad qTh/kTh cols 65..71
    if (t < 224) {
        int d = t >> 3, c = t & 7;
        if (c < 7) { qTh[d * 72 + 65 + c] = __float2half(0.f); kTh[d * 72 + 65 + c] = __float2half(0.f); }
        if (d < 28) { int d2 = 28 + (t & 3), c2 = (t >> 2) % 7; (void)d2; (void)c2; }
    }
    // cover remaining rows 28..31 pads via second range
    if (t >= 224 && t < 252) {
        int r = t - 224;             // 0..27 -> rows 28..31, cols 65..71
        int d = 28 + r / 7, c = r % 7;
        qTh[d * 72 + 65 + c] = __float2half(0.f);
        kTh[d * 72 + 65 + c] = __float2half(0.f);
    }
    const __half* base = g_qkvh + (size_t)(b * NTOK) * 3072 + h * DIM_HEAD;
    for (int e = t; e < NTOK * 16; e += 256) {
        int n = e >> 4, p = e & 15;
        __half2 qh = *(const __half2*)(base + (size_t)n * 3072 + p * 2);
        __half2 kh = *(const __half2*)(base + (size_t)n * 3072 + 1024 + p * 2);
        __half2 vh = *(const __half2*)(base + (size_t)n * 3072 + 2048 + p * 2);
        qTh[(2 * p) * 72 + n] = __low2half(qh);  qTh[(2 * p + 1) * 72 + n] = __high2half(qh);
        kTh[(2 * p) * 72 + n] = __low2half(kh);  kTh[(2 * p + 1) * 72 + n] = __high2half(kh);
        *(__half2*)&vsph[n * 40 + 2 * p] = vh;
    }
    __syncthreads();
    const float* bias = g_bias + (size_t)h * NN;
    // sim: 17 ti x 9 tj tiles of 4i x 8j (single pass, 153 items)
    if (t < 153) {
        int ti = t / 9, tj = t - ti * 9;
        int i0 = ti * 4, j0 = tj * 8;
        float aj[8][4];
        #pragma unroll
        for (int jj = 0; jj < 8; jj++)
            #pragma unroll
            for (int ii = 0; ii < 4; ii++) aj[jj][ii] = 0.f;
        #pragma unroll
        for (int d = 0; d < DIM_HEAD; d++) {
            float2 q01 = __half22float2(*(const __half2*)&qTh[d * 72 + i0]);
            float2 q23 = __half22float2(*(const __half2*)&qTh[d * 72 + i0 + 2]);
            float qv[4] = {q01.x, q01.y, q23.x, q23.y};
            float4 kraw = *(const float4*)&kTh[d * 72 + j0];
            const __half2* kh = (const __half2*)&kraw;
            #pragma unroll
            for (int jp = 0; jp < 4; jp++) {
                float2 kf = __half22float2(kh[jp]);
                #pragma unroll
                for (int ii = 0; ii < 4; ii++) {
                    aj[2*jp][ii]   = fmaf(qv[ii], kf.x, aj[2*jp][ii]);
                    aj[2*jp+1][ii] = fmaf(qv[ii], kf.y, aj[2*jp+1][ii]);
                }
            }
        }
        int i1 = (i0 + 1 < NTOK) ? i0 + 1 : NTOK - 1;
        int i2 = (i0 + 2 < NTOK) ? i0 + 2 : NTOK - 1;
        int i3 = (i0 + 3 < NTOK) ? i0 + 3 : NTOK - 1;
        #pragma unroll
        for (int jj = 0; jj < 8; jj++) {
            int j = j0 + jj;
            if (j < NTOK) {
                float4 o;
                o.x = aj[jj][0] + bias[i0 * NTOK + j];
                o.y = aj[jj][1] + bias[i1 * NTOK + j];
                o.z = aj[jj][2] + bias[i2 * NTOK + j];
                o.w = aj[jj][3] + bias[i3 * NTOK + j];
                *(float4*)&psT[j * 68 + i0] = o;
            }
        }
    }
    __syncthreads();
    if (t < NTOK) {
        float mx = -1e30f;
        #pragma unroll 5
        for (int j = 0; j < NTOK; j++) mx = fmaxf(mx, psT[j * 68 + t]);
        float sum = 0.f;
        #pragma unroll 5
        for (int j = 0; j < NTOK; j++) {
            float p = __expf(psT[j * 68 + t] - mx); psT[j * 68 + t] = p; sum += p;
        }
        float inv = 1.f / sum;
        #pragma unroll 5
        for (int j = 0; j < NTOK; j++) psT[j * 68 + t] *= inv;
    }
    __syncthreads();
    // PV: 17 ti x 4 dg tiles of 4i x 8d (68 items)
    if (t < 68) {
        int ti = t >> 2, dg = t & 3;
        int i0 = ti * 4, d0 = dg * 8;
        float ad[4][8];
        #pragma unroll
        for (int ii = 0; ii < 4; ii++)
            #pragma unroll
            for (int dd = 0; dd < 8; dd++) ad[ii][dd] = 0.f;
        #pragma unroll 5
        for (int j = 0; j < NTOK; j++) {
            float4 pp = *(const float4*)&psT[j * 68 + i0];
            float pc[4] = {pp.x, pp.y, pp.z, pp.w};
            float4 vraw = *(const float4*)&vsph[j * 40 + d0];
            const __half2* vh = (const __half2*)&vraw;
            float vf[8];
            #pragma unroll
            for (int vp = 0; vp < 4; vp++) {
                float2 v2 = __half22float2(vh[vp]);
                vf[2*vp] = v2.x; vf[2*vp+1] = v2.y;
            }
            #pragma unroll
            for (int ii = 0; ii < 4; ii++)
                #pragma unroll
                for (int dd = 0; dd < 8; dd++)
                    ad[ii][dd] = fmaf(pc[ii], vf[dd], ad[ii][dd]);
        }
        #pragma unroll
        for (int ii = 0; ii < 4; ii++) {
            int i = i0 + ii;
            if (i < NTOK) {
                __half2 h2[4];
                #pragma unroll
                for (int vp = 0; vp < 4; vp++)
                    h2[vp] = __floats2half2_rn(ad[ii][2*vp], ad[ii][2*vp+1]);
                *(uint4*)(g_oh + (size_t)(b * NTOK + i) * DIMX + h * DIM_HEAD + d0) =
                    *(uint4*)h2;
            }
        }
    }
}

extern "C" void kernel_launch(void* const* d_in, const int* in_sizes, int n_in,
                              void* d_out, int out_size)
{
    const float* x       = (const float*)d_in[0];
    const float* cond    = (const float*)d_in[1];
    const float* fw1     = (const float*)d_in[2];
    const float* fb1     = (const float*)d_in[3];
    const float* fw2     = (const float*)d_in[4];
    const float* fb2     = (const float*)d_in[5];
    const float* wqkv    = (const float*)d_in[6];
    const float* qg      = (const float*)d_in[7];
    const float* kg      = (const float*)d_in[8];
    const float* rel_emb = (const float*)d_in[9];
    const float* wout    = (const float*)d_in[10];
    const int*   rel_idx = (const int*)d_in[11];
    float* out = (float*)d_out;

    __half *p_xnh, *p_oh, *p_wqkvT, *p_woutT, *p_qkvh;
    cudaGetSymbolAddress((void**)&p_xnh,   g_xnh);
    cudaGetSymbolAddress((void**)&p_qkvh,  g_qkvh);
    cudaGetSymbolAddress((void**)&p_oh,    g_oh);
    cudaGetSymbolAddress((void**)&p_wqkvT, g_wqkvT);
    cudaGetSymbolAddress((void**)&p_woutT, g_woutT);

    cudaFuncSetAttribute(hgemm_kernel<0>, cudaFuncAttributeMaxDynamicSharedMemorySize, HG_SMEM);
    cudaFuncSetAttribute(hgemm_kernel<1>, cudaFuncAttributeMaxDynamicSharedMemorySize, HG_SMEM);

    // order: prep(1), film2(2), ln(3), hgemm_qkv(4)=ncu capture, attn(5), hgemm_out(6)
    prep_kernel<<<4096 + 128 + 17, 256>>>(wqkv, wout, cond, fw1, fb1, rel_emb, rel_idx);
    film2_kernel<<<dim3(8, B_IMG), 256>>>(fw2, fb2);
    ln_film_kernel<<<M_TOK, 256>>>(x);

    hgemm_kernel<1><<<dim3(3 * DIMX / 128, M_TOK / 128), 256, HG_SMEM>>>(
        p_xnh, p_wqkvT, p_qkvh, qg, kg, 3 * DIMX, DIMX);

    attn_kernel<<<dim3(B_TOT, HEADS), 256>>>();

    hgemm_kernel<0><<<dim3(DIMX / 128, M_TOK / 128), 256, HG_SMEM>>>(
        p_oh, p_woutT, out, nullptr, nullptr, DIMX, DIMX);
}

// round 17
// speedup vs baseline: 1.0410x; 1.0410x over previous
#include <cuda_runtime.h>
#include <cuda_fp16.h>
#include <math.h>
#include <stdint.h>

#define DIMX 1024
#define COND_DIM 512
#define HEADS 32
#define DIM_HEAD 32
#define NTOK 65
#define B_TOT 512
#define B_IMG 16
#define M_TOK (B_TOT * NTOK)
#define TWO_DIM (2 * DIMX)
#define NN (NTOK * NTOK)

__device__ float  g_h1[B_IMG * TWO_DIM];
__device__ float  g_gb[B_IMG * TWO_DIM];
__device__ __half g_xnh[(size_t)M_TOK * DIMX];
__device__ __half g_qkvh[(size_t)M_TOK * 3 * DIMX];
__device__ __half g_oh[(size_t)M_TOK * DIMX];
__device__ __half g_wqkvT[(size_t)3 * DIMX * DIMX];
__device__ __half g_woutT[(size_t)DIMX * DIMX];
__device__ float  g_bias[HEADS * NN];

#define CPA16(d, s) asm volatile("cp.async.cg.shared.global [%0], [%1], 16;" :: "r"(d), "l"(s) : "memory")
#define CPC()   asm volatile("cp.async.commit_group;" ::: "memory")
#define CPW0()  asm volatile("cp.async.wait_group 0;" ::: "memory")
#define CPW1()  asm volatile("cp.async.wait_group 1;" ::: "memory")
#define LDSM4(r0,r1,r2,r3,a) asm volatile( \
    "ldmatrix.sync.aligned.m8n8.x4.shared.b16 {%0,%1,%2,%3}, [%4];" \
    : "=r"(r0),"=r"(r1),"=r"(r2),"=r"(r3) : "r"(a))

__device__ __forceinline__ uint32_t smem_u32(const void* p) {
    uint32_t a; asm("{ .reg .u64 t; cvta.to.shared.u64 t, %1; cvt.u32.u64 %0, t; }" : "=r"(a) : "l"(p));
    return a;
}
__device__ __forceinline__ void mma_f16(float* d, const uint32_t* a, const uint32_t* b) {
    asm volatile(
        "mma.sync.aligned.m16n8k16.row.col.f32.f16.f16.f32 "
        "{%0,%1,%2,%3}, {%4,%5,%6,%7}, {%8,%9}, {%0,%1,%2,%3};\n"
        : "+f"(d[0]), "+f"(d[1]), "+f"(d[2]), "+f"(d[3])
        : "r"(a[0]), "r"(a[1]), "r"(a[2]), "r"(a[3]), "r"(b[0]), "r"(b[1]));
}

// ---- prep: wtrans (4096) + film1 (128) + bias (17) ----
__global__ __launch_bounds__(256) void prep_kernel(
    const float* __restrict__ Wq, const float* __restrict__ Wo,
    const float* __restrict__ cond, const float* __restrict__ w1, const float* __restrict__ b1,
    const float* __restrict__ rel_emb, const int* __restrict__ rel_idx)
{
    const int bx = blockIdx.x, t = threadIdx.x;
    if (bx < 4096) {
        __shared__ float tbuf[32][33];
        int bxx = bx & 127, byy = bx >> 7;
        int tx = t & 31, ty = t >> 5;
        const float* W;
        __half* WT;
        int N, n0;
        if (bxx < 96) { W = Wq; WT = g_wqkvT; N = 3 * DIMX; n0 = bxx * 32; }
        else          { W = Wo; WT = g_woutT; N = DIMX;     n0 = (bxx - 96) * 32; }
        int k0 = byy * 32;
        #pragma unroll
        for (int r = 0; r < 32; r += 8)
            tbuf[ty + r][tx] = W[(size_t)(k0 + ty + r) * N + n0 + tx];
        __syncthreads();
        #pragma unroll
        for (int r = 0; r < 32; r += 8)
            WT[(size_t)(n0 + ty + r) * DIMX + k0 + tx] = __float2half_rn(tbuf[tx][ty + r]);
    } else if (bx < 4096 + 128) {
        __shared__ float cs[COND_DIM];
        int i = (bx - 4096) >> 3, jb = (bx - 4096) & 7;
        int j = jb * 256 + t;
        for (int k = t; k < COND_DIM; k += 256) cs[k] = cond[i * COND_DIM + k];
        __syncthreads();
        float acc = b1[j];
        #pragma unroll 8
        for (int k = 0; k < COND_DIM; k++)
            acc = fmaf(cs[k], w1[(size_t)k * TWO_DIM + j], acc);
        g_h1[i * TWO_DIM + j] = acc / (1.f + __expf(-acc));
    } else {
        int e = (bx - 4096 - 128) * 256 + t;
        if (e < NN) {
            const float* re = rel_emb + (size_t)rel_idx[e] * HEADS;
            #pragma unroll
            for (int h = 0; h < HEADS; h++) g_bias[h * NN + e] = re[h];
        }
    }
}

// ---- FiLM stage 2 ----
__global__ __launch_bounds__(256) void film2_kernel(
    const float* __restrict__ w2, const float* __restrict__ b2)
{
    __shared__ float hs[TWO_DIM];
    int t = threadIdx.x, i = blockIdx.y;
    int j = blockIdx.x * 256 + t;
    for (int k = t; k < TWO_DIM; k += 256) hs[k] = g_h1[i * TWO_DIM + k];
    __syncthreads();
    float acc = b2[j];
    #pragma unroll 8
    for (int k = 0; k < TWO_DIM; k++)
        acc = fmaf(hs[k], w2[(size_t)k * TWO_DIM + j], acc);
    g_gb[i * TWO_DIM + j] = acc;
}

// ---- LayerNorm + FiLM -> half ----
__global__ __launch_bounds__(256) void ln_film_kernel(const float* __restrict__ x)
{
    int row = blockIdx.x;
    int img = (row / NTOK) >> 5;
    const float4* xr = (const float4*)(x + (size_t)row * DIMX);
    int t = threadIdx.x;
    float4 v = xr[t];
    float s = v.x + v.y + v.z + v.w;
    float ss = v.x*v.x + v.y*v.y + v.z*v.z + v.w*v.w;
    __shared__ float rs_[8], rss[8];
    #pragma unroll
    for (int o = 16; o > 0; o >>= 1) {
        s += __shfl_down_sync(~0u, s, o); ss += __shfl_down_sync(~0u, ss, o);
    }
    int warp = t >> 5, lane = t & 31;
    if (lane == 0) { rs_[warp] = s; rss[warp] = ss; }
    __syncthreads();
    if (warp == 0) {
        s = (lane < 8) ? rs_[lane] : 0.f; ss = (lane < 8) ? rss[lane] : 0.f;
        #pragma unroll
        for (int o = 4; o > 0; o >>= 1) {
            s += __shfl_down_sync(~0u, s, o); ss += __shfl_down_sync(~0u, ss, o);
        }
        if (lane == 0) { rs_[0] = s; rss[0] = ss; }
    }
    __syncthreads();
    float mu = rs_[0] * (1.f / DIMX);
    float var = rss[0] * (1.f / DIMX) - mu * mu;
    float rstd = rsqrtf(var + 1e-5f);
    const float4* gam = (const float4*)(g_gb + (size_t)img * TWO_DIM);
    const float4* bet = (const float4*)(g_gb + (size_t)img * TWO_DIM + DIMX);
    float4 gv = gam[t], bv = bet[t];
    __half2 h0 = __floats2half2_rn(fmaf((v.x - mu) * rstd, gv.x, bv.x),
                                   fmaf((v.y - mu) * rstd, gv.y, bv.y));
    __half2 h1 = __floats2half2_rn(fmaf((v.z - mu) * rstd, gv.z, bv.z),
                                   fmaf((v.w - mu) * rstd, gv.w, bv.w));
    ((__half2*)(g_xnh + (size_t)row * DIMX))[t * 2]     = h0;
    ((__half2*)(g_xnh + (size_t)row * DIMX))[t * 2 + 1] = h1;
}

// ---- fp16 GEMM 128x128x64, 3-stage cp.async, single barrier, LDSM4 A+B (R16) ----
#define ASTR 72
#define TILE_B (128 * ASTR * 2)      // 18432
#define STG_B (2 * TILE_B)           // 36864
#define HG_SMEM (3 * STG_B)          // 110592

template <int FUSE>
__global__ __launch_bounds__(256, 2) void hgemm_kernel(
    const __half* __restrict__ A, const __half* __restrict__ Bt,
    void* __restrict__ Cv, const float* __restrict__ qgam,
    const float* __restrict__ kgam, int N, int K)
{
    extern __shared__ char sm[];
    const uint32_t sb = smem_u32(sm);
    const int tid = threadIdx.x, warp = tid >> 5, lane = tid & 31;
    const int g = lane >> 2, tig = lane & 3;
    const int wm = (warp & 1) * 64, wn = (warp >> 1) * 32;
    const int row0 = blockIdx.y * 128, col0 = blockIdx.x * 128;

    float acc[4][4][4];
    #pragma unroll
    for (int mi = 0; mi < 4; mi++)
        #pragma unroll
        for (int nj = 0; nj < 4; nj++)
            #pragma unroll
            for (int c = 0; c < 4; c++) acc[mi][nj][c] = 0.f;

    const uint32_t laneA  = (uint32_t)((lane & 15) * 144 + (lane >> 4) * 16);
    const uint32_t laneB4 = (uint32_t)(((lane & 7) + ((lane >> 4) << 3)) * 144 + ((lane >> 3) & 1) * 16);

    const int KITERS = K >> 6;
    #pragma unroll
    for (int s = 0; s < 2; s++) {
        const int k0 = s << 6;
        #pragma unroll
        for (int p = 0; p < 4; p++) {
            int c = tid + 256 * p;
            int row = c >> 3, off = c & 7;
            CPA16(sb + s * STG_B + row * 144 + off * 16,
                  A + (size_t)(row0 + row) * K + k0 + off * 8);
            CPA16(sb + s * STG_B + TILE_B + row * 144 + off * 16,
                  Bt + (size_t)(col0 + row) * K + k0 + off * 8);
        }
        CPC();
    }
    int s_rd = 0, s_wr = 2;
    for (int kt = 0; kt < KITERS; kt++) {
        if (kt >= KITERS - 2) { CPW0(); } else { CPW1(); }
        __syncthreads();
        if (kt + 2 < KITERS) {
            const int k0 = (kt + 2) << 6;
            #pragma unroll
            for (int p = 0; p < 4; p++) {
                int c = tid + 256 * p;
                int row = c >> 3, off = c & 7;
                CPA16(sb + s_wr * STG_B + row * 144 + off * 16,
                      A + (size_t)(row0 + row) * K + k0 + off * 8);
                CPA16(sb + s_wr * STG_B + TILE_B + row * 144 + off * 16,
                      Bt + (size_t)(col0 + row) * K + k0 + off * 8);
            }
            CPC();
        }
        const uint32_t stA = sb + s_rd * STG_B;
        const uint32_t stB = stA + TILE_B;
        #pragma unroll
        for (int kk = 0; kk < 4; kk++) {
            uint32_t af[4][4], bf[4][2];
            #pragma unroll
            for (int mi = 0; mi < 4; mi++) {
                uint32_t a = stA + (uint32_t)(wm + mi * 16) * 144 + kk * 32 + laneA;
                LDSM4(af[mi][0], af[mi][1], af[mi][2], af[mi][3], a);
            }
            #pragma unroll
            for (int njp = 0; njp < 2; njp++) {
                uint32_t a = stB + (uint32_t)(wn + njp * 16) * 144 + kk * 32 + laneB4;
                LDSM4(bf[2*njp][0], bf[2*njp][1], bf[2*njp+1][0], bf[2*njp+1][1], a);
            }
            #pragma unroll
            for (int mi = 0; mi < 4; mi++)
                #pragma unroll
                for (int nj = 0; nj < 4; nj++)
                    mma_f16(acc[mi][nj], af[mi], bf[nj]);
        }
        s_rd = (s_rd == 2) ? 0 : s_rd + 1;
        s_wr = (s_wr == 2) ? 0 : s_wr + 1;
    }
    if (FUSE == 0) {
        float* C = (float*)Cv;
        #pragma unroll
        for (int mi = 0; mi < 4; mi++) {
            #pragma unroll
            for (int nj = 0; nj < 4; nj++) {
                int r = row0 + wm + mi * 16 + g;
                int c = col0 + wn + nj * 8 + tig * 2;
                *(float2*)(C + (size_t)r * N + c)       = make_float2(acc[mi][nj][0], acc[mi][nj][1]);
                *(float2*)(C + (size_t)(r + 8) * N + c) = make_float2(acc[mi][nj][2], acc[mi][nj][3]);
            }
        }
    } else {
        __half* C = (__half*)Cv;
        const int gcol0 = col0 + wn;
        const int sec = gcol0 >> 10;
        const int head = (gcol0 & 1023) >> 5;
        float gam[8];
        #pragma unroll
        for (int nj = 0; nj < 4; nj++) {
            int d = nj * 8 + tig * 2;
            if (sec == 0)      { gam[nj*2] = qgam[head*32+d]; gam[nj*2+1] = qgam[head*32+d+1]; }
            else if (sec == 1) { gam[nj*2] = kgam[head*32+d]; gam[nj*2+1] = kgam[head*32+d+1]; }
            else               { gam[nj*2] = 1.f; gam[nj*2+1] = 1.f; }
        }
        #pragma unroll
        for (int mi = 0; mi < 4; mi++) {
            #pragma unroll
            for (int hf = 0; hf < 2; hf++) {
                int r = row0 + wm + mi * 16 + g + hf * 8;
                float ss = 0.f;
                #pragma unroll
                for (int nj = 0; nj < 4; nj++) {
                    float a0 = acc[mi][nj][hf*2], a1 = acc[mi][nj][hf*2+1];
                    ss = fmaf(a0, a0, ss); ss = fmaf(a1, a1, ss);
                }
                ss += __shfl_xor_sync(~0u, ss, 1);
                ss += __shfl_xor_sync(~0u, ss, 2);
                float sc = (sec < 2) ? 5.656854249f / fmaxf(sqrtf(ss), 1e-12f) : 1.f;
                #pragma unroll
                for (int nj = 0; nj < 4; nj++) {
                    __half2 h2 = __floats2half2_rn(acc[mi][nj][hf*2]   * sc * gam[nj*2],
                                                   acc[mi][nj][hf*2+1] * sc * gam[nj*2+1]);
                    *(__half2*)(C + (size_t)r * 3072 + gcol0 + nj * 8 + tig * 2) = h2;
                }
            }
        }
    }
}

// ---- attention: R15 version (float smem, 4x4 register tiles) ----
#define OFF_QT 4624
#define OFF_KT 6800
#define OFF_VS 8976
__global__ __launch_bounds__(256) void attn_kernel()
{
    int b = blockIdx.x, h = blockIdx.y;
    __shared__ __align__(16) float smf[11316];
    float* psT = smf;
    float* qT  = smf + OFF_QT;
    float* kT  = smf + OFF_KT;
    float* vsp = smf + OFF_VS;

    int t = threadIdx.x;
    if (t < 192) {
        int which = t / 96, r = t % 96;
        int d = r & 31, c = r >> 5;
        (which ? kT : qT)[d * 68 + 65 + c] = 0.f;
    }
    const __half* base = g_qkvh + (size_t)(b * NTOK) * 3072 + h * DIM_HEAD;
    for (int e = t; e < NTOK * 16; e += 256) {
        int n = e >> 4, p = e & 15;
        float2 qf = __half22float2(*(const __half2*)(base + (size_t)n * 3072 + p * 2));
        float2 kf = __half22float2(*(const __half2*)(base + (size_t)n * 3072 + 1024 + p * 2));
        float2 vf = __half22float2(*(const __half2*)(base + (size_t)n * 3072 + 2048 + p * 2));
        qT[(2 * p) * 68 + n] = qf.x; qT[(2 * p + 1) * 68 + n] = qf.y;
        kT[(2 * p) * 68 + n] = kf.x; kT[(2 * p + 1) * 68 + n] = kf.y;
        vsp[n * 36 + 2 * p] = vf.x;  vsp[n * 36 + 2 * p + 1] = vf.y;
    }
    __syncthreads();
    const float* bias = g_bias + (size_t)h * NN;
    #pragma unroll
    for (int it = 0; it < 2; it++) {
        int item = it * 256 + t;
        if (item < 289) {
            int ti = item / 17, tj = item - ti * 17;
            int i0 = ti * 4, j0 = tj * 4;
            float4 aj[4];
            #pragma unroll
            for (int jj = 0; jj < 4; jj++) aj[jj] = make_float4(0.f, 0.f, 0.f, 0.f);
            #pragma unroll
            for (int d = 0; d < DIM_HEAD; d++) {
                float4 qv = *(const float4*)&qT[d * 68 + i0];
                float4 kv = *(const float4*)&kT[d * 68 + j0];
                float kc[4] = {kv.x, kv.y, kv.z, kv.w};
                #pragma unroll
                for (int jj = 0; jj < 4; jj++) {
                    aj[jj].x = fmaf(qv.x, kc[jj], aj[jj].x);
                    aj[jj].y = fmaf(qv.y, kc[jj], aj[jj].y);
                    aj[jj].z = fmaf(qv.z, kc[jj], aj[jj].z);
                    aj[jj].w = fmaf(qv.w, kc[jj], aj[jj].w);
                }
            }
            #pragma unroll
            for (int jj = 0; jj < 4; jj++) {
                int j = j0 + jj;
                if (j < NTOK) {
                    int i1 = (i0 + 1 < NTOK) ? i0 + 1 : NTOK - 1;
                    int i2 = (i0 + 2 < NTOK) ? i0 + 2 : NTOK - 1;
                    int i3 = (i0 + 3 < NTOK) ? i0 + 3 : NTOK - 1;
                    float4 o;
                    o.x = aj[jj].x + bias[i0 * NTOK + j];
                    o.y = aj[jj].y + bias[i1 * NTOK + j];
                    o.z = aj[jj].z + bias[i2 * NTOK + j];
                    o.w = aj[jj].w + bias[i3 * NTOK + j];
                    *(float4*)&psT[j * 68 + i0] = o;
                }
            }
        }
    }
    __syncthreads();
    if (t < NTOK) {
        float mx = -1e30f;
        #pragma unroll 5
        for (int j = 0; j < NTOK; j++) mx = fmaxf(mx, psT[j * 68 + t]);
        float sum = 0.f;
        #pragma unroll 5
        for (int j = 0; j < NTOK; j++) {
            float p = __expf(psT[j * 68 + t] - mx); psT[j * 68 + t] = p; sum += p;
        }
        float inv = 1.f / sum;
        #pragma unroll 5
        for (int j = 0; j < NTOK; j++) psT[j * 68 + t] *= inv;
    }
    __syncthreads();
    if (t < 136) {
        int ti = t >> 3, dg = t & 7;
        int i0 = ti * 4;
        float4 ad[4];
        #pragma unroll
        for (int ii = 0; ii < 4; ii++) ad[ii] = make_float4(0.f, 0.f, 0.f, 0.f);
        #pragma unroll 5
        for (int j = 0; j < NTOK; j++) {
            float4 pp = *(const float4*)&psT[j * 68 + i0];
            float4 vv = *(const float4*)&vsp[j * 36 + dg * 4];
            float pc[4] = {pp.x, pp.y, pp.z, pp.w};
            #pragma unroll
            for (int ii = 0; ii < 4; ii++) {
                ad[ii].x = fmaf(pc[ii], vv.x, ad[ii].x);
                ad[ii].y = fmaf(pc[ii], vv.y, ad[ii].y);
                ad[ii].z = fmaf(pc[ii], vv.z, ad[ii].z);
                ad[ii].w = fmaf(pc[ii], vv.w, ad[ii].w);
            }
        }
        #pragma unroll
        for (int ii = 0; ii < 4; ii++) {
            int i = i0 + ii;
            if (i < NTOK) {
                __half* op = g_oh + (size_t)(b * NTOK + i) * DIMX + h * DIM_HEAD + dg * 4;
                *(__half2*)op       = __floats2half2_rn(ad[ii].x, ad[ii].y);
                *(__half2*)(op + 2) = __floats2half2_rn(ad[ii].z, ad[ii].w);
            }
        }
    }
}

extern "C" void kernel_launch(void* const* d_in, const int* in_sizes, int n_in,
                              void* d_out, int out_size)
{
    const float* x       = (const float*)d_in[0];
    const float* cond    = (const float*)d_in[1];
    const float* fw1     = (const float*)d_in[2];
    const float* fb1     = (const float*)d_in[3];
    const float* fw2     = (const float*)d_in[4];
    const float* fb2     = (const float*)d_in[5];
    const float* wqkv    = (const float*)d_in[6];
    const float* qg      = (const float*)d_in[7];
    const float* kg      = (const float*)d_in[8];
    const float* rel_emb = (const float*)d_in[9];
    const float* wout    = (const float*)d_in[10];
    const int*   rel_idx = (const int*)d_in[11];
    float* out = (float*)d_out;

    __half *p_xnh, *p_oh, *p_wqkvT, *p_woutT, *p_qkvh;
    cudaGetSymbolAddress((void**)&p_xnh,   g_xnh);
    cudaGetSymbolAddress((void**)&p_qkvh,  g_qkvh);
    cudaGetSymbolAddress((void**)&p_oh,    g_oh);
    cudaGetSymbolAddress((void**)&p_wqkvT, g_wqkvT);
    cudaGetSymbolAddress((void**)&p_woutT, g_woutT);

    cudaFuncSetAttribute(hgemm_kernel<0>, cudaFuncAttributeMaxDynamicSharedMemorySize, HG_SMEM);
    cudaFuncSetAttribute(hgemm_kernel<1>, cudaFuncAttributeMaxDynamicSharedMemorySize, HG_SMEM);

    // order: prep(1), film2(2), ln(3), hgemm_qkv(4)=ncu capture, attn(5), hgemm_out(6)
    prep_kernel<<<4096 + 128 + 17, 256>>>(wqkv, wout, cond, fw1, fb1, rel_emb, rel_idx);
    film2_kernel<<<dim3(8, B_IMG), 256>>>(fw2, fb2);
    ln_film_kernel<<<M_TOK, 256>>>(x);

    hgemm_kernel<1><<<dim3(3 * DIMX / 128, M_TOK / 128), 256, HG_SMEM>>>(
        p_xnh, p_wqkvT, p_qkvh, qg, kg, 3 * DIMX, DIMX);

    attn_kernel<<<dim3(B_TOT, HEADS), 256>>>();

    hgemm_kernel<0><<<dim3(DIMX / 128, M_TOK / 128), 256, HG_SMEM>>>(
        p_oh, p_woutT, out, nullptr, nullptr, DIMX, DIMX);
}